// round 10
// baseline (speedup 1.0000x reference)
#include <cuda_runtime.h>
#include <cstdint>

// ---------------------------------------------------------------------------
// GenerativeUpsample: per-batch kth-smallest threshold on pred, prune fea.
//   fea:  [N, 64] f32   d_in[0]
//   pred: [N, 1]  f32   d_in[1]
//   bid:  [N]     i32   d_in[2]  (sorted)
//   tgt:  [B]     i32   d_in[3]
// out: [N*64] pruned fea, then (if room) [N] keep as 0/1 float.
//
// Exact 2-level (16+16 bit) radix select on monotone uint key of pred.
// R7 launch structure (proven best); prune is grid-stride persistent
// (one wave of CTAs) with ILP=2 per iteration.
// ---------------------------------------------------------------------------

#define MAXB 8
#define NBIN 65536
#define NSEG 64
#define SEGBINS 1024

__device__ __align__(16) unsigned g_hist1[MAXB * NBIN];
__device__ __align__(16) unsigned g_hist2[MAXB * NBIN];
__device__ unsigned g_seg[MAXB * NSEG];
__device__ int      g_off[MAXB + 1];
__device__ unsigned g_selBin[MAXB];
__device__ unsigned g_selRank[MAXB];
__device__ int      g_active[MAXB];
__device__ unsigned g_threshKey[MAXB];

__device__ __forceinline__ unsigned f2key(float f) {
    unsigned u = __float_as_uint(f);
    return (u & 0x80000000u) ? ~u : (u | 0x80000000u);
}

__device__ __forceinline__ int batch_of(int i, const int* o) {
    int b = 0;
    #pragma unroll
    for (int k = 1; k < MAXB; k++) b += (i >= o[k]);
    return b;
}

// block-wide (256 thr) exclusive scan; wsum = 8-word smem scratch.
__device__ __forceinline__ unsigned scan_excl(unsigned val, int tid,
                                              unsigned* wsum) {
    int lane = tid & 31, wid = tid >> 5;
    unsigned x = val;
    #pragma unroll
    for (int d = 1; d < 32; d <<= 1) {
        unsigned y = __shfl_up_sync(0xFFFFFFFFu, x, d);
        if (lane >= d) x += y;
    }
    if (lane == 31) wsum[wid] = x;
    __syncthreads();
    if (tid == 0) {
        unsigned a = 0;
        #pragma unroll
        for (int w = 0; w < 8; w++) { unsigned t = wsum[w]; wsum[w] = a; a += t; }
    }
    __syncthreads();
    return wsum[wid] + x - val;
}

// -------- batch boundaries via binary search (bids sorted) -----------------
__global__ void k_bounds(const int* __restrict__ bid, int n) {
    int t = threadIdx.x;
    if (t > MAXB) return;
    if (t == MAXB) { g_off[MAXB] = n; return; }
    int lo = 0, hi = n;
    while (lo < hi) {
        int mid = (lo + hi) >> 1;
        if (bid[mid] < t) lo = mid + 1; else hi = mid;
    }
    g_off[t] = lo;
}

// -------- pass 1: top-16-bit histogram, float4 loads -----------------------
__global__ void k_hist1(const float4* __restrict__ pred4, int n4) {
    __shared__ int soff[MAXB + 1];
    if (threadIdx.x <= MAXB) soff[threadIdx.x] = g_off[threadIdx.x];
    __syncthreads();
    int o[MAXB + 1];
    #pragma unroll
    for (int k = 0; k <= MAXB; k++) o[k] = soff[k];

    for (int i4 = blockIdx.x * blockDim.x + threadIdx.x; i4 < n4;
         i4 += gridDim.x * blockDim.x) {
        float4 p = pred4[i4];
        int base = i4 * 4;
        float pv[4] = {p.x, p.y, p.z, p.w};
        #pragma unroll
        for (int j = 0; j < 4; j++) {
            int b = batch_of(base + j, o);
            atomicAdd(&g_hist1[b * NBIN + (f2key(pv[j]) >> 16)], 1u);
        }
    }
}

// -------- pass 2: low-16-bit histogram of in-selected-bin elements ---------
__global__ void k_hist2(const float4* __restrict__ pred4, int n4) {
    __shared__ int soff[MAXB + 1];
    __shared__ unsigned ssel[MAXB];
    if (threadIdx.x <= MAXB) soff[threadIdx.x] = g_off[threadIdx.x];
    if (threadIdx.x < MAXB)  ssel[threadIdx.x] = g_selBin[threadIdx.x];
    __syncthreads();
    int o[MAXB + 1];
    #pragma unroll
    for (int k = 0; k <= MAXB; k++) o[k] = soff[k];

    for (int i4 = blockIdx.x * blockDim.x + threadIdx.x; i4 < n4;
         i4 += gridDim.x * blockDim.x) {
        float4 p = pred4[i4];
        int base = i4 * 4;
        float pv[4] = {p.x, p.y, p.z, p.w};
        #pragma unroll
        for (int j = 0; j < 4; j++) {
            int b = batch_of(base + j, o);
            unsigned key = f2key(pv[j]);
            if ((key >> 16) == ssel[b])
                atomicAdd(&g_hist2[b * NBIN + (key & 0xFFFFu)], 1u);
        }
    }
}

// -------- coarse segment sums: 8 batches x 64 segs = 512 blocks ------------
__global__ void k_coarse(int which) {
    const unsigned* hist = (which == 1) ? g_hist1 : g_hist2;
    int b = blockIdx.x >> 6;
    int s = blockIdx.x & 63;
    const uint4* h4 = (const uint4*)&hist[b * NBIN + s * SEGBINS];
    uint4 v = h4[threadIdx.x];
    unsigned sum = v.x + v.y + v.z + v.w;
    #pragma unroll
    for (int d = 16; d > 0; d >>= 1) sum += __shfl_down_sync(0xFFFFFFFFu, sum, d);
    __shared__ unsigned ws[8];
    if ((threadIdx.x & 31) == 0) ws[threadIdx.x >> 5] = sum;
    __syncthreads();
    if (threadIdx.x == 0) {
        unsigned t = 0;
        #pragma unroll
        for (int w = 0; w < 8; w++) t += ws[w];
        g_seg[b * NSEG + s] = t;
    }
}

// -------- walk: parallel scan-based selection, 8 blocks x 256 thr ----------
__global__ void k_walk(int level, const int* __restrict__ tgt) {
    const unsigned* hist = (level == 1) ? g_hist1 : g_hist2;
    int b = blockIdx.x;
    int tid = threadIdx.x;
    __shared__ unsigned wsum[8];
    __shared__ int sact;
    __shared__ unsigned srank;
    __shared__ int ssegi;
    __shared__ unsigned srank2;

    if (tid == 0) {
        long long rank;
        int act;
        if (level == 1) {
            int nn = g_off[b + 1] - g_off[b];
            int t = tgt[b];
            act = (nn > t);
            rank = (long long)nn - t - 1;
        } else {
            act = g_active[b];
            rank = (long long)g_selRank[b];
        }
        sact = act;
        srank = (unsigned)rank;
    }
    __syncthreads();
    if (!sact) {
        if (tid == 0) {
            if (level == 1) {
                g_active[b] = 0;
                g_selBin[b] = 0xFFFFFFFFu;  // matches nothing in pass 2
                g_selRank[b] = 0;
            } else {
                g_threshKey[b] = 0u;  // every real key > 0 -> keep all
            }
        }
        return;
    }

    // level A: pick segment among 64 seg-sums
    unsigned v = (tid < NSEG) ? g_seg[b * NSEG + tid] : 0u;
    unsigned e = scan_excl(v, tid, wsum);
    unsigned r = srank;
    if (r >= e && r < e + v) { ssegi = tid; srank2 = r - e; }
    __syncthreads();

    // level B: pick bin among 1024 bins of the segment (4/thread)
    const uint4* h4 = (const uint4*)&hist[b * NBIN + ssegi * SEGBINS];
    uint4 q = h4[tid];
    unsigned v2 = q.x + q.y + q.z + q.w;
    unsigned e2 = scan_excl(v2, tid, wsum);
    unsigned r2 = srank2;
    if (r2 >= e2 && r2 < e2 + v2) {
        unsigned rr = r2 - e2;
        unsigned bvals[4] = {q.x, q.y, q.z, q.w};
        int j = 0;
        while (rr >= bvals[j]) { rr -= bvals[j]; j++; }
        unsigned bin = (unsigned)(ssegi * SEGBINS + tid * 4 + j);
        if (level == 1) {
            g_selBin[b] = bin;
            g_selRank[b] = rr;
            g_active[b] = 1;
        } else {
            g_threshKey[b] = (g_selBin[b] << 16) | bin;
        }
    }
}

// -------- grid-stride persistent prune: ILP=2, skip dropped reads ----------
#define PRUNE_BLOCKS 592
#define PRUNE_THREADS 512
__global__ void __launch_bounds__(PRUNE_THREADS)
k_prune(const float4* __restrict__ fea4,
        const float* __restrict__ pred,
        float4* __restrict__ out4,
        float* __restrict__ out_keep,
        int total2, int writeKeep) {
    __shared__ unsigned sthr[MAXB];
    __shared__ int soff[MAXB + 1];
    if (threadIdx.x < MAXB) sthr[threadIdx.x] = g_threshKey[threadIdx.x];
    if (threadIdx.x >= 32 && threadIdx.x <= 32 + MAXB)
        soff[threadIdx.x - 32] = g_off[threadIdx.x - 32];
    __syncthreads();

    int o[MAXB + 1];
    #pragma unroll
    for (int k = 0; k <= MAXB; k++) o[k] = soff[k];
    unsigned thr[MAXB];
    #pragma unroll
    for (int k = 0; k < MAXB; k++) thr[k] = sthr[k];

    const int tid0 = blockIdx.x * blockDim.x + threadIdx.x;
    const int stride = gridDim.x * blockDim.x;

    // scratch re-zero for next invocation (graph replay determinism)
    {
        const int ZW = (MAXB * NBIN) / 4;  // uint4 words per hist
        if (tid0 < ZW) {
            ((uint4*)g_hist1)[tid0] = make_uint4(0u, 0u, 0u, 0u);
        } else if (tid0 < 2 * ZW) {
            ((uint4*)g_hist2)[tid0 - ZW] = make_uint4(0u, 0u, 0u, 0u);
        }
    }

    for (int gid = tid0; gid < total2; gid += stride) {
        int row = gid >> 3;  // 8 threads per 64-wide row (2 float4 each)
        int b = batch_of(row, o);
        unsigned key = f2key(pred[row]);
        bool keep = key > thr[b];

        float4 v0 = make_float4(0.f, 0.f, 0.f, 0.f);
        float4 v1 = v0;
        if (keep) {  // dropped rows: no fea read (output is zeros there)
            v0 = __ldcs(&fea4[2 * gid]);
            v1 = __ldcs(&fea4[2 * gid + 1]);
        }
        __stcs(&out4[2 * gid], v0);
        __stcs(&out4[2 * gid + 1], v1);
        if (writeKeep && ((gid & 7) == 0)) out_keep[row] = keep ? 1.0f : 0.0f;
    }
}

extern "C" void kernel_launch(void* const* d_in, const int* in_sizes, int n_in,
                              void* d_out, int out_size) {
    const float* fea  = (const float*)d_in[0];
    const float* pred = (const float*)d_in[1];
    const int*   bid  = (const int*)d_in[2];
    const int*   tgt  = (const int*)d_in[3];
    const int n = in_sizes[1];      // N points
    const int C = in_sizes[0] / n;  // 64

    float* out_fea  = (float*)d_out;
    int writeKeep = (out_size >= n * C + n) ? 1 : 0;
    float* out_keep = out_fea + (size_t)n * C;

    k_bounds<<<1, 32>>>(bid, n);
    int n4 = n / 4;
    k_hist1<<<(n4 + 255) / 256, 256>>>((const float4*)pred, n4);
    k_coarse<<<MAXB * NSEG, 256>>>(1);
    k_walk<<<MAXB, 256>>>(1, tgt);
    k_hist2<<<(n4 + 255) / 256, 256>>>((const float4*)pred, n4);
    k_coarse<<<MAXB * NSEG, 256>>>(2);
    k_walk<<<MAXB, 256>>>(2, tgt);

    int total2 = n * (C / 8);  // ILP=2 work items
    k_prune<<<PRUNE_BLOCKS, PRUNE_THREADS>>>((const float4*)fea, pred,
                                             (float4*)d_out, out_keep,
                                             total2, writeKeep);
}

// round 11
// speedup vs baseline: 1.0620x; 1.0620x over previous
#include <cuda_runtime.h>
#include <cstdint>

// ---------------------------------------------------------------------------
// GenerativeUpsample: per-batch kth-smallest threshold on pred, prune fea.
//   fea:  [N, 64] f32   d_in[0]
//   pred: [N, 1]  f32   d_in[1]
//   bid:  [N]     i32   d_in[2]  (sorted)
//   tgt:  [B]     i32   d_in[3]
// out: [N*64] pruned fea, then (if room) [N] keep as 0/1 float.
//
// Exact 2-level (16+16 bit) radix select on monotone uint key of pred.
// Persistent grid-stride prune, ILP=2, thresholds in SHARED memory inside
// the loop (R10's register-array version spilled to local memory).
// ---------------------------------------------------------------------------

#define MAXB 8
#define NBIN 65536
#define NSEG 64
#define SEGBINS 1024

__device__ __align__(16) unsigned g_hist1[MAXB * NBIN];
__device__ __align__(16) unsigned g_hist2[MAXB * NBIN];
__device__ unsigned g_seg[MAXB * NSEG];
__device__ int      g_off[MAXB + 1];
__device__ unsigned g_selBin[MAXB];
__device__ unsigned g_selRank[MAXB];
__device__ int      g_active[MAXB];
__device__ unsigned g_threshKey[MAXB];

__device__ __forceinline__ unsigned f2key(float f) {
    unsigned u = __float_as_uint(f);
    return (u & 0x80000000u) ? ~u : (u | 0x80000000u);
}

__device__ __forceinline__ int batch_of(int i, const int* o) {
    int b = 0;
    #pragma unroll
    for (int k = 1; k < MAXB; k++) b += (i >= o[k]);
    return b;
}

// block-wide (256 thr) exclusive scan; wsum = 8-word smem scratch.
__device__ __forceinline__ unsigned scan_excl(unsigned val, int tid,
                                              unsigned* wsum) {
    int lane = tid & 31, wid = tid >> 5;
    unsigned x = val;
    #pragma unroll
    for (int d = 1; d < 32; d <<= 1) {
        unsigned y = __shfl_up_sync(0xFFFFFFFFu, x, d);
        if (lane >= d) x += y;
    }
    if (lane == 31) wsum[wid] = x;
    __syncthreads();
    if (tid == 0) {
        unsigned a = 0;
        #pragma unroll
        for (int w = 0; w < 8; w++) { unsigned t = wsum[w]; wsum[w] = a; a += t; }
    }
    __syncthreads();
    return wsum[wid] + x - val;
}

// -------- batch boundaries via binary search (bids sorted) -----------------
__global__ void k_bounds(const int* __restrict__ bid, int n) {
    int t = threadIdx.x;
    if (t > MAXB) return;
    if (t == MAXB) { g_off[MAXB] = n; return; }
    int lo = 0, hi = n;
    while (lo < hi) {
        int mid = (lo + hi) >> 1;
        if (bid[mid] < t) lo = mid + 1; else hi = mid;
    }
    g_off[t] = lo;
}

// -------- pass 1: top-16-bit histogram, float4 loads -----------------------
__global__ void k_hist1(const float4* __restrict__ pred4, int n4) {
    __shared__ int soff[MAXB + 1];
    if (threadIdx.x <= MAXB) soff[threadIdx.x] = g_off[threadIdx.x];
    __syncthreads();
    int o[MAXB + 1];
    #pragma unroll
    for (int k = 0; k <= MAXB; k++) o[k] = soff[k];

    for (int i4 = blockIdx.x * blockDim.x + threadIdx.x; i4 < n4;
         i4 += gridDim.x * blockDim.x) {
        float4 p = pred4[i4];
        int base = i4 * 4;
        float pv[4] = {p.x, p.y, p.z, p.w};
        #pragma unroll
        for (int j = 0; j < 4; j++) {
            int b = batch_of(base + j, o);
            atomicAdd(&g_hist1[b * NBIN + (f2key(pv[j]) >> 16)], 1u);
        }
    }
}

// -------- pass 2: low-16-bit histogram of in-selected-bin elements ---------
__global__ void k_hist2(const float4* __restrict__ pred4, int n4) {
    __shared__ int soff[MAXB + 1];
    __shared__ unsigned ssel[MAXB];
    if (threadIdx.x <= MAXB) soff[threadIdx.x] = g_off[threadIdx.x];
    if (threadIdx.x < MAXB)  ssel[threadIdx.x] = g_selBin[threadIdx.x];
    __syncthreads();
    int o[MAXB + 1];
    #pragma unroll
    for (int k = 0; k <= MAXB; k++) o[k] = soff[k];

    for (int i4 = blockIdx.x * blockDim.x + threadIdx.x; i4 < n4;
         i4 += gridDim.x * blockDim.x) {
        float4 p = pred4[i4];
        int base = i4 * 4;
        float pv[4] = {p.x, p.y, p.z, p.w};
        #pragma unroll
        for (int j = 0; j < 4; j++) {
            int b = batch_of(base + j, o);
            unsigned key = f2key(pv[j]);
            if ((key >> 16) == ssel[b])
                atomicAdd(&g_hist2[b * NBIN + (key & 0xFFFFu)], 1u);
        }
    }
}

// -------- coarse segment sums: 8 batches x 64 segs = 512 blocks ------------
__global__ void k_coarse(int which) {
    const unsigned* hist = (which == 1) ? g_hist1 : g_hist2;
    int b = blockIdx.x >> 6;
    int s = blockIdx.x & 63;
    const uint4* h4 = (const uint4*)&hist[b * NBIN + s * SEGBINS];
    uint4 v = h4[threadIdx.x];
    unsigned sum = v.x + v.y + v.z + v.w;
    #pragma unroll
    for (int d = 16; d > 0; d >>= 1) sum += __shfl_down_sync(0xFFFFFFFFu, sum, d);
    __shared__ unsigned ws[8];
    if ((threadIdx.x & 31) == 0) ws[threadIdx.x >> 5] = sum;
    __syncthreads();
    if (threadIdx.x == 0) {
        unsigned t = 0;
        #pragma unroll
        for (int w = 0; w < 8; w++) t += ws[w];
        g_seg[b * NSEG + s] = t;
    }
}

// -------- walk: parallel scan-based selection, 8 blocks x 256 thr ----------
__global__ void k_walk(int level, const int* __restrict__ tgt) {
    const unsigned* hist = (level == 1) ? g_hist1 : g_hist2;
    int b = blockIdx.x;
    int tid = threadIdx.x;
    __shared__ unsigned wsum[8];
    __shared__ int sact;
    __shared__ unsigned srank;
    __shared__ int ssegi;
    __shared__ unsigned srank2;

    if (tid == 0) {
        long long rank;
        int act;
        if (level == 1) {
            int nn = g_off[b + 1] - g_off[b];
            int t = tgt[b];
            act = (nn > t);
            rank = (long long)nn - t - 1;
        } else {
            act = g_active[b];
            rank = (long long)g_selRank[b];
        }
        sact = act;
        srank = (unsigned)rank;
    }
    __syncthreads();
    if (!sact) {
        if (tid == 0) {
            if (level == 1) {
                g_active[b] = 0;
                g_selBin[b] = 0xFFFFFFFFu;  // matches nothing in pass 2
                g_selRank[b] = 0;
            } else {
                g_threshKey[b] = 0u;  // every real key > 0 -> keep all
            }
        }
        return;
    }

    // level A: pick segment among 64 seg-sums
    unsigned v = (tid < NSEG) ? g_seg[b * NSEG + tid] : 0u;
    unsigned e = scan_excl(v, tid, wsum);
    unsigned r = srank;
    if (r >= e && r < e + v) { ssegi = tid; srank2 = r - e; }
    __syncthreads();

    // level B: pick bin among 1024 bins of the segment (4/thread)
    const uint4* h4 = (const uint4*)&hist[b * NBIN + ssegi * SEGBINS];
    uint4 q = h4[tid];
    unsigned v2 = q.x + q.y + q.z + q.w;
    unsigned e2 = scan_excl(v2, tid, wsum);
    unsigned r2 = srank2;
    if (r2 >= e2 && r2 < e2 + v2) {
        unsigned rr = r2 - e2;
        unsigned bvals[4] = {q.x, q.y, q.z, q.w};
        int j = 0;
        while (rr >= bvals[j]) { rr -= bvals[j]; j++; }
        unsigned bin = (unsigned)(ssegi * SEGBINS + tid * 4 + j);
        if (level == 1) {
            g_selBin[b] = bin;
            g_selRank[b] = rr;
            g_active[b] = 1;
        } else {
            g_threshKey[b] = (g_selBin[b] << 16) | bin;
        }
    }
}

// -------- persistent grid-stride prune: ILP=2, thresholds in SMEM ----------
#define PRUNE_BLOCKS 592
#define PRUNE_THREADS 512
__global__ void __launch_bounds__(PRUNE_THREADS)
k_prune(const float4* __restrict__ fea4,
        const float* __restrict__ pred,
        float4* __restrict__ out4,
        float* __restrict__ out_keep,
        int total2, int writeKeep) {
    __shared__ unsigned sthr[MAXB];
    __shared__ int soff[MAXB + 1];
    if (threadIdx.x < MAXB) sthr[threadIdx.x] = g_threshKey[threadIdx.x];
    if (threadIdx.x >= 32 && threadIdx.x <= 32 + MAXB)
        soff[threadIdx.x - 32] = g_off[threadIdx.x - 32];
    __syncthreads();

    // static-unrolled offset compares (registers, no dynamic indexing)
    int o[MAXB + 1];
    #pragma unroll
    for (int k = 0; k <= MAXB; k++) o[k] = soff[k];

    const int tid0 = blockIdx.x * blockDim.x + threadIdx.x;
    const int stride = gridDim.x * blockDim.x;

    // scratch re-zero for next invocation (graph replay determinism)
    {
        const int ZW = (MAXB * NBIN) / 4;  // uint4 words per hist
        if (tid0 < ZW) {
            ((uint4*)g_hist1)[tid0] = make_uint4(0u, 0u, 0u, 0u);
        } else if (tid0 < 2 * ZW) {
            ((uint4*)g_hist2)[tid0 - ZW] = make_uint4(0u, 0u, 0u, 0u);
        }
    }

    for (int gid = tid0; gid < total2; gid += stride) {
        int row = gid >> 3;  // 8 threads per 64-wide row (2 float4 each)
        int b = batch_of(row, o);
        unsigned key = f2key(pred[row]);
        bool keep = key > sthr[b];  // SMEM dynamic index (no spill)

        float4 v0 = make_float4(0.f, 0.f, 0.f, 0.f);
        float4 v1 = v0;
        if (keep) {  // dropped rows: no fea read (output is zeros there)
            v0 = __ldcs(&fea4[2 * gid]);
            v1 = __ldcs(&fea4[2 * gid + 1]);
        }
        __stcs(&out4[2 * gid], v0);
        __stcs(&out4[2 * gid + 1], v1);
        if (writeKeep && ((gid & 7) == 0)) out_keep[row] = keep ? 1.0f : 0.0f;
    }
}

extern "C" void kernel_launch(void* const* d_in, const int* in_sizes, int n_in,
                              void* d_out, int out_size) {
    const float* fea  = (const float*)d_in[0];
    const float* pred = (const float*)d_in[1];
    const int*   bid  = (const int*)d_in[2];
    const int*   tgt  = (const int*)d_in[3];
    const int n = in_sizes[1];      // N points
    const int C = in_sizes[0] / n;  // 64

    float* out_fea  = (float*)d_out;
    int writeKeep = (out_size >= n * C + n) ? 1 : 0;
    float* out_keep = out_fea + (size_t)n * C;

    k_bounds<<<1, 32>>>(bid, n);
    int n4 = n / 4;
    k_hist1<<<(n4 + 255) / 256, 256>>>((const float4*)pred, n4);
    k_coarse<<<MAXB * NSEG, 256>>>(1);
    k_walk<<<MAXB, 256>>>(1, tgt);
    k_hist2<<<(n4 + 255) / 256, 256>>>((const float4*)pred, n4);
    k_coarse<<<MAXB * NSEG, 256>>>(2);
    k_walk<<<MAXB, 256>>>(2, tgt);

    int total2 = n * (C / 8);  // ILP=2 work items
    k_prune<<<PRUNE_BLOCKS, PRUNE_THREADS>>>((const float4*)fea, pred,
                                             (float4*)d_out, out_keep,
                                             total2, writeKeep);
}

// round 12
// speedup vs baseline: 1.2519x; 1.1787x over previous
#include <cuda_runtime.h>
#include <cstdint>

// ---------------------------------------------------------------------------
// GenerativeUpsample: per-batch kth-smallest threshold on pred, prune fea.
//   fea:  [N, 64] f32   d_in[0]
//   pred: [N, 1]  f32   d_in[1]
//   bid:  [N]     i32   d_in[2]  (sorted, values in [0,B))
//   tgt:  [B]     i32   d_in[3]
// out: [N*64] pruned fea, then (if room) [N] keep as 0/1 float.
//
// Exact select on monotone uint key of pred:
//   hist1 (top 16 bits) -> coarse -> walk1 -> collect (in-bin keys, tiny)
//   -> final (smem radix over <=CAP keys) -> prune.
// 6 launches. Scratch zeroed at load + re-zeroed by prune for graph replay.
// ---------------------------------------------------------------------------

#define MAXB 8
#define NBIN 65536
#define NSEG 64
#define SEGBINS 1024
#define CAP 8192

__device__ __align__(16) unsigned g_hist1[MAXB * NBIN];
__device__ __align__(16) unsigned g_vals[MAXB * CAP];
__device__ unsigned g_cnt[MAXB];
__device__ unsigned g_seg[MAXB * NSEG];
__device__ unsigned g_selBin[MAXB];
__device__ unsigned g_selRank[MAXB];
__device__ int      g_active[MAXB];
__device__ unsigned g_threshKey[MAXB];

__device__ __forceinline__ unsigned f2key(float f) {
    unsigned u = __float_as_uint(f);
    return (u & 0x80000000u) ? ~u : (u | 0x80000000u);
}

// block-wide (256 thr) exclusive scan; wsum = 8-word smem scratch.
__device__ __forceinline__ unsigned scan_excl(unsigned val, int tid,
                                              unsigned* wsum) {
    int lane = tid & 31, wid = tid >> 5;
    unsigned x = val;
    #pragma unroll
    for (int d = 1; d < 32; d <<= 1) {
        unsigned y = __shfl_up_sync(0xFFFFFFFFu, x, d);
        if (lane >= d) x += y;
    }
    if (lane == 31) wsum[wid] = x;
    __syncthreads();
    if (tid == 0) {
        unsigned a = 0;
        #pragma unroll
        for (int w = 0; w < 8; w++) { unsigned t = wsum[w]; wsum[w] = a; a += t; }
    }
    __syncthreads();
    return wsum[wid] + x - val;
}

// -------- pass 1: top-16-bit histogram; batch from bid loads ---------------
__global__ void k_hist1(const float4* __restrict__ pred4,
                        const uint4* __restrict__ bid4, int n4) {
    for (int i4 = blockIdx.x * blockDim.x + threadIdx.x; i4 < n4;
         i4 += gridDim.x * blockDim.x) {
        float4 p = pred4[i4];
        uint4 bb = bid4[i4];
        float pv[4] = {p.x, p.y, p.z, p.w};
        unsigned bv[4] = {bb.x, bb.y, bb.z, bb.w};
        #pragma unroll
        for (int j = 0; j < 4; j++)
            atomicAdd(&g_hist1[bv[j] * NBIN + (f2key(pv[j]) >> 16)], 1u);
    }
}

// -------- coarse segment sums: 8 batches x 64 segs = 512 blocks ------------
__global__ void k_coarse() {
    int b = blockIdx.x >> 6;
    int s = blockIdx.x & 63;
    const uint4* h4 = (const uint4*)&g_hist1[b * NBIN + s * SEGBINS];
    uint4 v = h4[threadIdx.x];
    unsigned sum = v.x + v.y + v.z + v.w;
    #pragma unroll
    for (int d = 16; d > 0; d >>= 1) sum += __shfl_down_sync(0xFFFFFFFFu, sum, d);
    __shared__ unsigned ws[8];
    if ((threadIdx.x & 31) == 0) ws[threadIdx.x >> 5] = sum;
    __syncthreads();
    if (threadIdx.x == 0) {
        unsigned t = 0;
        #pragma unroll
        for (int w = 0; w < 8; w++) t += ws[w];
        g_seg[b * NSEG + s] = t;
    }
}

// -------- walk1: pick level-1 bin; count derived from seg totals -----------
__global__ void k_walk1(const int* __restrict__ tgt) {
    int b = blockIdx.x;
    int tid = threadIdx.x;
    __shared__ unsigned wsum[8];
    __shared__ unsigned stotal;
    __shared__ int ssegi;
    __shared__ unsigned srank2;

    // level A: 64 seg-sums; scan gives both total (count) and prefix
    unsigned v = (tid < NSEG) ? g_seg[b * NSEG + tid] : 0u;
    unsigned e = scan_excl(v, tid, wsum);
    if (tid == NSEG - 1) stotal = e + v;
    __syncthreads();

    int nn = (int)stotal;
    int t = tgt[b];
    if (nn <= t) {
        if (tid == 0) {
            g_active[b] = 0;
            g_selBin[b] = 0xFFFFFFFFu;  // matches no key>>16 (max 0xFFFF)
            g_selRank[b] = 0;
        }
        return;
    }
    unsigned rank = (unsigned)(nn - t - 1);  // 0-indexed kth
    if (tid == 0) g_active[b] = 1;
    if (rank >= e && rank < e + v) { ssegi = tid; srank2 = rank - e; }
    __syncthreads();

    // level B: 1024 bins of the chosen segment, 4 per thread
    const uint4* h4 = (const uint4*)&g_hist1[b * NBIN + ssegi * SEGBINS];
    uint4 q = h4[tid];
    unsigned v2 = q.x + q.y + q.z + q.w;
    unsigned e2 = scan_excl(v2, tid, wsum);
    unsigned r2 = srank2;
    if (r2 >= e2 && r2 < e2 + v2) {
        unsigned rr = r2 - e2;
        unsigned bvals[4] = {q.x, q.y, q.z, q.w};
        int j = 0;
        while (rr >= bvals[j]) { rr -= bvals[j]; j++; }
        g_selBin[b] = (unsigned)(ssegi * SEGBINS + tid * 4 + j);
        g_selRank[b] = rr;
    }
}

// -------- collect: append keys whose top 16 bits hit the selected bin ------
__global__ void k_collect(const float4* __restrict__ pred4,
                          const uint4* __restrict__ bid4, int n4) {
    __shared__ unsigned ssel[MAXB];
    if (threadIdx.x < MAXB) ssel[threadIdx.x] = g_selBin[threadIdx.x];
    __syncthreads();

    for (int i4 = blockIdx.x * blockDim.x + threadIdx.x; i4 < n4;
         i4 += gridDim.x * blockDim.x) {
        float4 p = pred4[i4];
        uint4 bb = bid4[i4];
        float pv[4] = {p.x, p.y, p.z, p.w};
        unsigned bv[4] = {bb.x, bb.y, bb.z, bb.w};
        #pragma unroll
        for (int j = 0; j < 4; j++) {
            unsigned key = f2key(pv[j]);
            unsigned b = bv[j];
            if ((key >> 16) == ssel[b]) {
                unsigned idx = atomicAdd(&g_cnt[b], 1u);
                if (idx < CAP) g_vals[b * CAP + idx] = key;
            }
        }
    }
}

// -------- final: smem 2x8-bit radix select over <=CAP in-bin keys ----------
__global__ void k_final() {
    int b = blockIdx.x;
    int tid = threadIdx.x;  // 256 threads
    __shared__ unsigned svals[CAP];   // low-16 bits of collected keys
    __shared__ unsigned shist[256];
    __shared__ unsigned wsum[8];
    __shared__ int sb1;
    __shared__ unsigned srank2;

    if (!g_active[b]) {
        if (tid == 0) g_threshKey[b] = 0u;  // every real key > 0 -> keep all
        return;
    }
    int cnt = (int)min(g_cnt[b], (unsigned)CAP);
    unsigned rank = g_selRank[b];

    for (int i = tid; i < cnt; i += 256)
        svals[i] = g_vals[b * CAP + i] & 0xFFFFu;
    shist[tid] = 0u;
    __syncthreads();

    // stage 1: histogram of bits [8:16)
    for (int i = tid; i < cnt; i += 256)
        atomicAdd(&shist[svals[i] >> 8], 1u);
    __syncthreads();
    unsigned v = shist[tid];
    unsigned e = scan_excl(v, tid, wsum);
    if (rank >= e && rank < e + v) { sb1 = tid; srank2 = rank - e; }
    __syncthreads();
    int b1 = sb1;
    unsigned rank2 = srank2;

    // stage 2: histogram of bits [0:8) among elements with byte1 == b1
    shist[tid] = 0u;
    __syncthreads();
    for (int i = tid; i < cnt; i += 256)
        if ((int)(svals[i] >> 8) == b1) atomicAdd(&shist[svals[i] & 0xFFu], 1u);
    __syncthreads();
    v = shist[tid];
    e = scan_excl(v, tid, wsum);
    if (rank2 >= e && rank2 < e + v)
        g_threshKey[b] = (g_selBin[b] << 16) | ((unsigned)b1 << 8) | (unsigned)tid;
}

// -------- streaming prune: ILP=2, skip fea reads for dropped rows ----------
__global__ void k_prune(const float4* __restrict__ fea4,
                        const float* __restrict__ pred,
                        const int* __restrict__ bid,
                        float4* __restrict__ out4,
                        float* __restrict__ out_keep,
                        int total2, int writeKeep) {
    __shared__ unsigned sthr[MAXB];
    if (threadIdx.x < MAXB) sthr[threadIdx.x] = g_threshKey[threadIdx.x];
    __syncthreads();

    int gid = blockIdx.x * blockDim.x + threadIdx.x;

    // fold scratch re-zero for next invocation (graph replay determinism)
    {
        const int ZW = (MAXB * NBIN) / 4;  // uint4 words in g_hist1
        if (gid < ZW) {
            ((uint4*)g_hist1)[gid] = make_uint4(0u, 0u, 0u, 0u);
        } else if (gid < ZW + MAXB) {
            g_cnt[gid - ZW] = 0u;
        }
    }

    if (gid >= total2) return;
    int row = gid >> 3;  // 8 threads per 64-wide row (2 float4 each)
    int b = bid[row];
    unsigned key = f2key(pred[row]);
    bool keep = key > sthr[b];

    float4 v0 = make_float4(0.f, 0.f, 0.f, 0.f);
    float4 v1 = v0;
    if (keep) {  // dropped rows: no fea read (output is zeros there)
        v0 = __ldcs(&fea4[2 * gid]);
        v1 = __ldcs(&fea4[2 * gid + 1]);
    }
    __stcs(&out4[2 * gid], v0);
    __stcs(&out4[2 * gid + 1], v1);
    if (writeKeep && ((gid & 7) == 0)) out_keep[row] = keep ? 1.0f : 0.0f;
}

extern "C" void kernel_launch(void* const* d_in, const int* in_sizes, int n_in,
                              void* d_out, int out_size) {
    const float* fea  = (const float*)d_in[0];
    const float* pred = (const float*)d_in[1];
    const int*   bid  = (const int*)d_in[2];
    const int*   tgt  = (const int*)d_in[3];
    const int n = in_sizes[1];      // N points
    const int C = in_sizes[0] / n;  // 64

    float* out_fea  = (float*)d_out;
    int writeKeep = (out_size >= n * C + n) ? 1 : 0;
    float* out_keep = out_fea + (size_t)n * C;

    int n4 = n / 4;
    k_hist1<<<(n4 + 255) / 256, 256>>>((const float4*)pred,
                                       (const uint4*)bid, n4);
    k_coarse<<<MAXB * NSEG, 256>>>();
    k_walk1<<<MAXB, 256>>>(tgt);
    k_collect<<<(n4 + 255) / 256, 256>>>((const float4*)pred,
                                         (const uint4*)bid, n4);
    k_final<<<MAXB, 256>>>();

    int total2 = n * (C / 8);  // ILP=2 work items
    k_prune<<<(total2 + 511) / 512, 512>>>((const float4*)fea, pred, bid,
                                           (float4*)d_out, out_keep,
                                           total2, writeKeep);
}

// round 13
// speedup vs baseline: 1.2790x; 1.0216x over previous
#include <cuda_runtime.h>
#include <cstdint>

// ---------------------------------------------------------------------------
// GenerativeUpsample: per-batch kth-smallest threshold on pred, prune fea.
//   fea:  [N, 64] f32   d_in[0]
//   pred: [N, 1]  f32   d_in[1]
//   bid:  [N]     i32   d_in[2]  (sorted, values in [0,B))
//   tgt:  [B]     i32   d_in[3]
// out: [N*64] pruned fea, then (if room) [N] keep as 0/1 float.
//
// Exact select on monotone uint key of pred:
//   hist1 (top 16 bits) -> coarse -> walk1 -> collect (in-bin keys, tiny)
//   -> final (smem radix over <=CAP keys) -> prune.
// 6 launches. Scratch zeroed at load + re-zeroed by prune for graph replay.
// ---------------------------------------------------------------------------

#define MAXB 8
#define NBIN 65536
#define NSEG 64
#define SEGBINS 1024
#define CAP 8192

__device__ __align__(16) unsigned g_hist1[MAXB * NBIN];
__device__ __align__(16) unsigned g_vals[MAXB * CAP];
__device__ unsigned g_cnt[MAXB];
__device__ unsigned g_seg[MAXB * NSEG];
__device__ unsigned g_selBin[MAXB];
__device__ unsigned g_selRank[MAXB];
__device__ int      g_active[MAXB];
__device__ unsigned g_threshKey[MAXB];

__device__ __forceinline__ unsigned f2key(float f) {
    unsigned u = __float_as_uint(f);
    return (u & 0x80000000u) ? ~u : (u | 0x80000000u);
}

// block-wide (256 thr) exclusive scan; wsum = 8-word smem scratch.
__device__ __forceinline__ unsigned scan_excl(unsigned val, int tid,
                                              unsigned* wsum) {
    int lane = tid & 31, wid = tid >> 5;
    unsigned x = val;
    #pragma unroll
    for (int d = 1; d < 32; d <<= 1) {
        unsigned y = __shfl_up_sync(0xFFFFFFFFu, x, d);
        if (lane >= d) x += y;
    }
    if (lane == 31) wsum[wid] = x;
    __syncthreads();
    if (tid == 0) {
        unsigned a = 0;
        #pragma unroll
        for (int w = 0; w < 8; w++) { unsigned t = wsum[w]; wsum[w] = a; a += t; }
    }
    __syncthreads();
    return wsum[wid] + x - val;
}

// -------- pass 1: top-16-bit histogram; batch from bid loads ---------------
__global__ void k_hist1(const float4* __restrict__ pred4,
                        const uint4* __restrict__ bid4, int n4) {
    for (int i4 = blockIdx.x * blockDim.x + threadIdx.x; i4 < n4;
         i4 += gridDim.x * blockDim.x) {
        float4 p = pred4[i4];
        uint4 bb = bid4[i4];
        float pv[4] = {p.x, p.y, p.z, p.w};
        unsigned bv[4] = {bb.x, bb.y, bb.z, bb.w};
        #pragma unroll
        for (int j = 0; j < 4; j++)
            atomicAdd(&g_hist1[bv[j] * NBIN + (f2key(pv[j]) >> 16)], 1u);
    }
}

// -------- coarse segment sums: 8 batches x 64 segs = 512 blocks ------------
__global__ void k_coarse() {
    int b = blockIdx.x >> 6;
    int s = blockIdx.x & 63;
    const uint4* h4 = (const uint4*)&g_hist1[b * NBIN + s * SEGBINS];
    uint4 v = h4[threadIdx.x];
    unsigned sum = v.x + v.y + v.z + v.w;
    #pragma unroll
    for (int d = 16; d > 0; d >>= 1) sum += __shfl_down_sync(0xFFFFFFFFu, sum, d);
    __shared__ unsigned ws[8];
    if ((threadIdx.x & 31) == 0) ws[threadIdx.x >> 5] = sum;
    __syncthreads();
    if (threadIdx.x == 0) {
        unsigned t = 0;
        #pragma unroll
        for (int w = 0; w < 8; w++) t += ws[w];
        g_seg[b * NSEG + s] = t;
    }
}

// -------- walk1: pick level-1 bin; count derived from seg totals -----------
__global__ void k_walk1(const int* __restrict__ tgt) {
    int b = blockIdx.x;
    int tid = threadIdx.x;
    __shared__ unsigned wsum[8];
    __shared__ unsigned stotal;
    __shared__ int ssegi;
    __shared__ unsigned srank2;

    // level A: 64 seg-sums; scan gives both total (count) and prefix
    unsigned v = (tid < NSEG) ? g_seg[b * NSEG + tid] : 0u;
    unsigned e = scan_excl(v, tid, wsum);
    if (tid == NSEG - 1) stotal = e + v;
    __syncthreads();

    int nn = (int)stotal;
    int t = tgt[b];
    if (nn <= t) {
        if (tid == 0) {
            g_active[b] = 0;
            g_selBin[b] = 0xFFFFFFFFu;  // matches no key>>16 (max 0xFFFF)
            g_selRank[b] = 0;
        }
        return;
    }
    unsigned rank = (unsigned)(nn - t - 1);  // 0-indexed kth
    if (tid == 0) g_active[b] = 1;
    if (rank >= e && rank < e + v) { ssegi = tid; srank2 = rank - e; }
    __syncthreads();

    // level B: 1024 bins of the chosen segment, 4 per thread
    const uint4* h4 = (const uint4*)&g_hist1[b * NBIN + ssegi * SEGBINS];
    uint4 q = h4[tid];
    unsigned v2 = q.x + q.y + q.z + q.w;
    unsigned e2 = scan_excl(v2, tid, wsum);
    unsigned r2 = srank2;
    if (r2 >= e2 && r2 < e2 + v2) {
        unsigned rr = r2 - e2;
        unsigned bvals[4] = {q.x, q.y, q.z, q.w};
        int j = 0;
        while (rr >= bvals[j]) { rr -= bvals[j]; j++; }
        g_selBin[b] = (unsigned)(ssegi * SEGBINS + tid * 4 + j);
        g_selRank[b] = rr;
    }
}

// -------- collect: append keys whose top 16 bits hit the selected bin ------
__global__ void k_collect(const float4* __restrict__ pred4,
                          const uint4* __restrict__ bid4, int n4) {
    __shared__ unsigned ssel[MAXB];
    if (threadIdx.x < MAXB) ssel[threadIdx.x] = g_selBin[threadIdx.x];
    __syncthreads();

    for (int i4 = blockIdx.x * blockDim.x + threadIdx.x; i4 < n4;
         i4 += gridDim.x * blockDim.x) {
        float4 p = pred4[i4];
        uint4 bb = bid4[i4];
        float pv[4] = {p.x, p.y, p.z, p.w};
        unsigned bv[4] = {bb.x, bb.y, bb.z, bb.w};
        #pragma unroll
        for (int j = 0; j < 4; j++) {
            unsigned key = f2key(pv[j]);
            unsigned b = bv[j];
            if ((key >> 16) == ssel[b]) {
                unsigned idx = atomicAdd(&g_cnt[b], 1u);
                if (idx < CAP) g_vals[b * CAP + idx] = key;
            }
        }
    }
}

// -------- final: smem 2x8-bit radix select over <=CAP in-bin keys ----------
__global__ void k_final() {
    int b = blockIdx.x;
    int tid = threadIdx.x;  // 256 threads
    __shared__ unsigned svals[CAP];   // low-16 bits of collected keys
    __shared__ unsigned shist[256];
    __shared__ unsigned wsum[8];
    __shared__ int sb1;
    __shared__ unsigned srank2;

    if (!g_active[b]) {
        if (tid == 0) g_threshKey[b] = 0u;  // every real key > 0 -> keep all
        return;
    }
    int cnt = (int)min(g_cnt[b], (unsigned)CAP);
    unsigned rank = g_selRank[b];

    for (int i = tid; i < cnt; i += 256)
        svals[i] = g_vals[b * CAP + i] & 0xFFFFu;
    shist[tid] = 0u;
    __syncthreads();

    // stage 1: histogram of bits [8:16)
    for (int i = tid; i < cnt; i += 256)
        atomicAdd(&shist[svals[i] >> 8], 1u);
    __syncthreads();
    unsigned v = shist[tid];
    unsigned e = scan_excl(v, tid, wsum);
    if (rank >= e && rank < e + v) { sb1 = tid; srank2 = rank - e; }
    __syncthreads();
    int b1 = sb1;
    unsigned rank2 = srank2;

    // stage 2: histogram of bits [0:8) among elements with byte1 == b1
    shist[tid] = 0u;
    __syncthreads();
    for (int i = tid; i < cnt; i += 256)
        if ((int)(svals[i] >> 8) == b1) atomicAdd(&shist[svals[i] & 0xFFu], 1u);
    __syncthreads();
    v = shist[tid];
    e = scan_excl(v, tid, wsum);
    if (rank2 >= e && rank2 < e + v)
        g_threshKey[b] = (g_selBin[b] << 16) | ((unsigned)b1 << 8) | (unsigned)tid;
}

// -------- streaming prune: ILP=2, 256-thr CTAs, skip dropped reads ---------
__global__ void k_prune(const float4* __restrict__ fea4,
                        const float* __restrict__ pred,
                        const int* __restrict__ bid,
                        float4* __restrict__ out4,
                        float* __restrict__ out_keep,
                        int total2, int writeKeep) {
    __shared__ unsigned sthr[MAXB];
    if (threadIdx.x < MAXB) sthr[threadIdx.x] = g_threshKey[threadIdx.x];
    __syncthreads();

    int gid = blockIdx.x * blockDim.x + threadIdx.x;

    // fold scratch re-zero for next invocation (graph replay determinism)
    {
        const int ZW = (MAXB * NBIN) / 4;  // uint4 words in g_hist1
        if (gid < ZW) {
            ((uint4*)g_hist1)[gid] = make_uint4(0u, 0u, 0u, 0u);
        } else if (gid < ZW + MAXB) {
            g_cnt[gid - ZW] = 0u;
        }
    }

    if (gid >= total2) return;
    int row = gid >> 3;  // 8 threads per 64-wide row (2 float4 each)
    int b = bid[row];    // L2-resident after collect
    unsigned key = f2key(pred[row]);
    bool keep = key > sthr[b];

    float4 v0 = make_float4(0.f, 0.f, 0.f, 0.f);
    float4 v1 = v0;
    if (keep) {  // dropped rows: no fea read (output is zeros there)
        v0 = __ldcs(&fea4[2 * gid]);
        v1 = __ldcs(&fea4[2 * gid + 1]);
    }
    __stcs(&out4[2 * gid], v0);
    __stcs(&out4[2 * gid + 1], v1);
    if (writeKeep && ((gid & 7) == 0)) out_keep[row] = keep ? 1.0f : 0.0f;
}

extern "C" void kernel_launch(void* const* d_in, const int* in_sizes, int n_in,
                              void* d_out, int out_size) {
    const float* fea  = (const float*)d_in[0];
    const float* pred = (const float*)d_in[1];
    const int*   bid  = (const int*)d_in[2];
    const int*   tgt  = (const int*)d_in[3];
    const int n = in_sizes[1];      // N points
    const int C = in_sizes[0] / n;  // 64

    float* out_fea  = (float*)d_out;
    int writeKeep = (out_size >= n * C + n) ? 1 : 0;
    float* out_keep = out_fea + (size_t)n * C;

    int n4 = n / 4;
    k_hist1<<<(n4 + 255) / 256, 256>>>((const float4*)pred,
                                       (const uint4*)bid, n4);
    k_coarse<<<MAXB * NSEG, 256>>>();
    k_walk1<<<MAXB, 256>>>(tgt);
    k_collect<<<(n4 + 255) / 256, 256>>>((const float4*)pred,
                                         (const uint4*)bid, n4);
    k_final<<<MAXB, 256>>>();

    int total2 = n * (C / 8);  // ILP=2 work items
    k_prune<<<(total2 + 255) / 256, 256>>>((const float4*)fea, pred, bid,
                                           (float4*)d_out, out_keep,
                                           total2, writeKeep);
}

// round 14
// speedup vs baseline: 1.2805x; 1.0012x over previous
#include <cuda_runtime.h>
#include <cstdint>

// ---------------------------------------------------------------------------
// GenerativeUpsample: per-batch kth-smallest threshold on pred, prune fea.
//   fea:  [N, 64] f32   d_in[0]
//   pred: [N, 1]  f32   d_in[1]
//   bid:  [N]     i32   d_in[2]  (sorted, values in [0,B))
//   tgt:  [B]     i32   d_in[3]
// out: [N*64] pruned fea, then (if room) [N] keep as 0/1 float.
//
// Exact select on monotone uint key of pred:
//   hist1 (top16) -> coarse -> walk1 -> collect (keep bytes + in-bin keys)
//   -> final (smem radix, fixes deferred rows) -> prune (keep byte + stream).
// 6 launches. Scratch zeroed at load + re-zeroed by prune for graph replay.
// ---------------------------------------------------------------------------

#define MAXB 8
#define NBIN 65536
#define NSEG 64
#define SEGBINS 1024
#define CAP 8192
#define MAXN (1 << 21)

__device__ __align__(16) unsigned g_hist1[MAXB * NBIN];
__device__ __align__(16) unsigned g_vals[MAXB * CAP];   // in-bin keys
__device__ __align__(16) int      g_rows[MAXB * CAP];   // their row indices
__device__ __align__(16) unsigned char g_keep[MAXN];    // per-row keep byte
__device__ unsigned g_cnt[MAXB];
__device__ unsigned g_seg[MAXB * NSEG];
__device__ unsigned g_selBin[MAXB];
__device__ unsigned g_selRank[MAXB];
__device__ int      g_active[MAXB];

__device__ __forceinline__ unsigned f2key(float f) {
    unsigned u = __float_as_uint(f);
    return (u & 0x80000000u) ? ~u : (u | 0x80000000u);
}

// block-wide (256 thr) exclusive scan; wsum = 8-word smem scratch.
__device__ __forceinline__ unsigned scan_excl(unsigned val, int tid,
                                              unsigned* wsum) {
    int lane = tid & 31, wid = tid >> 5;
    unsigned x = val;
    #pragma unroll
    for (int d = 1; d < 32; d <<= 1) {
        unsigned y = __shfl_up_sync(0xFFFFFFFFu, x, d);
        if (lane >= d) x += y;
    }
    if (lane == 31) wsum[wid] = x;
    __syncthreads();
    if (tid == 0) {
        unsigned a = 0;
        #pragma unroll
        for (int w = 0; w < 8; w++) { unsigned t = wsum[w]; wsum[w] = a; a += t; }
    }
    __syncthreads();
    return wsum[wid] + x - val;
}

// -------- pass 1: top-16-bit histogram; batch from bid loads ---------------
__global__ void k_hist1(const float4* __restrict__ pred4,
                        const uint4* __restrict__ bid4, int n4) {
    for (int i4 = blockIdx.x * blockDim.x + threadIdx.x; i4 < n4;
         i4 += gridDim.x * blockDim.x) {
        float4 p = pred4[i4];
        uint4 bb = bid4[i4];
        float pv[4] = {p.x, p.y, p.z, p.w};
        unsigned bv[4] = {bb.x, bb.y, bb.z, bb.w};
        #pragma unroll
        for (int j = 0; j < 4; j++)
            atomicAdd(&g_hist1[bv[j] * NBIN + (f2key(pv[j]) >> 16)], 1u);
    }
}

// -------- coarse segment sums: 8 batches x 64 segs = 512 blocks ------------
__global__ void k_coarse() {
    int b = blockIdx.x >> 6;
    int s = blockIdx.x & 63;
    const uint4* h4 = (const uint4*)&g_hist1[b * NBIN + s * SEGBINS];
    uint4 v = h4[threadIdx.x];
    unsigned sum = v.x + v.y + v.z + v.w;
    #pragma unroll
    for (int d = 16; d > 0; d >>= 1) sum += __shfl_down_sync(0xFFFFFFFFu, sum, d);
    __shared__ unsigned ws[8];
    if ((threadIdx.x & 31) == 0) ws[threadIdx.x >> 5] = sum;
    __syncthreads();
    if (threadIdx.x == 0) {
        unsigned t = 0;
        #pragma unroll
        for (int w = 0; w < 8; w++) t += ws[w];
        g_seg[b * NSEG + s] = t;
    }
}

// -------- walk1: pick level-1 bin; count derived from seg totals -----------
__global__ void k_walk1(const int* __restrict__ tgt) {
    int b = blockIdx.x;
    int tid = threadIdx.x;
    __shared__ unsigned wsum[8];
    __shared__ unsigned stotal;
    __shared__ int ssegi;
    __shared__ unsigned srank2;

    // level A: 64 seg-sums; scan gives both total (count) and prefix
    unsigned v = (tid < NSEG) ? g_seg[b * NSEG + tid] : 0u;
    unsigned e = scan_excl(v, tid, wsum);
    if (tid == NSEG - 1) stotal = e + v;
    __syncthreads();

    int nn = (int)stotal;
    int t = tgt[b];
    if (nn <= t) {
        if (tid == 0) {
            g_active[b] = 0;
            g_selBin[b] = 0xFFFFFFFFu;  // collect: inactive -> keep all
            g_selRank[b] = 0;
        }
        return;
    }
    unsigned rank = (unsigned)(nn - t - 1);  // 0-indexed kth
    if (tid == 0) g_active[b] = 1;
    if (rank >= e && rank < e + v) { ssegi = tid; srank2 = rank - e; }
    __syncthreads();

    // level B: 1024 bins of the chosen segment, 4 per thread
    const uint4* h4 = (const uint4*)&g_hist1[b * NBIN + ssegi * SEGBINS];
    uint4 q = h4[tid];
    unsigned v2 = q.x + q.y + q.z + q.w;
    unsigned e2 = scan_excl(v2, tid, wsum);
    unsigned r2 = srank2;
    if (r2 >= e2 && r2 < e2 + v2) {
        unsigned rr = r2 - e2;
        unsigned bvals[4] = {q.x, q.y, q.z, q.w};
        int j = 0;
        while (rr >= bvals[j]) { rr -= bvals[j]; j++; }
        g_selBin[b] = (unsigned)(ssegi * SEGBINS + tid * 4 + j);
        g_selRank[b] = rr;
    }
}

// -------- collect: resolve keep bytes; stash in-bin (deferred) rows --------
__global__ void k_collect(const float4* __restrict__ pred4,
                          const uint4* __restrict__ bid4, int n4) {
    __shared__ unsigned ssel[MAXB];
    __shared__ int sact[MAXB];
    if (threadIdx.x < MAXB) {
        ssel[threadIdx.x] = g_selBin[threadIdx.x];
        sact[threadIdx.x] = g_active[threadIdx.x];
    }
    __syncthreads();

    for (int i4 = blockIdx.x * blockDim.x + threadIdx.x; i4 < n4;
         i4 += gridDim.x * blockDim.x) {
        float4 p = pred4[i4];
        uint4 bb = bid4[i4];
        float pv[4] = {p.x, p.y, p.z, p.w};
        unsigned bv[4] = {bb.x, bb.y, bb.z, bb.w};
        unsigned char kb[4];
        #pragma unroll
        for (int j = 0; j < 4; j++) {
            unsigned key = f2key(pv[j]);
            unsigned b = bv[j];
            unsigned top = key >> 16;
            if (!sact[b]) {
                kb[j] = 1;                 // no threshold -> keep all
            } else if (top > ssel[b]) {
                kb[j] = 1;
            } else if (top < ssel[b]) {
                kb[j] = 0;
            } else {                       // in selected bin: defer to final
                unsigned idx = atomicAdd(&g_cnt[b], 1u);
                if (idx < CAP) {
                    g_vals[b * CAP + idx] = key;
                    g_rows[b * CAP + idx] = i4 * 4 + j;
                }
                kb[j] = 0;
            }
        }
        uchar4 k4 = make_uchar4(kb[0], kb[1], kb[2], kb[3]);
        ((uchar4*)g_keep)[i4] = k4;
    }
}

// -------- final: smem radix over in-bin keys; fix deferred keep bytes ------
__global__ void k_final() {
    int b = blockIdx.x;
    int tid = threadIdx.x;  // 256 threads
    __shared__ unsigned svals[CAP];   // low-16 bits of collected keys
    __shared__ unsigned shist[256];
    __shared__ unsigned wsum[8];
    __shared__ int sb1;
    __shared__ unsigned srank2;
    __shared__ unsigned stlow;

    if (!g_active[b]) return;  // keep bytes already all 1 from collect
    int cnt = (int)min(g_cnt[b], (unsigned)CAP);
    unsigned rank = g_selRank[b];

    for (int i = tid; i < cnt; i += 256)
        svals[i] = g_vals[b * CAP + i] & 0xFFFFu;
    shist[tid] = 0u;
    __syncthreads();

    // stage 1: histogram of bits [8:16)
    for (int i = tid; i < cnt; i += 256)
        atomicAdd(&shist[svals[i] >> 8], 1u);
    __syncthreads();
    unsigned v = shist[tid];
    unsigned e = scan_excl(v, tid, wsum);
    if (rank >= e && rank < e + v) { sb1 = tid; srank2 = rank - e; }
    __syncthreads();
    int b1 = sb1;
    unsigned rank2 = srank2;

    // stage 2: histogram of bits [0:8) among elements with byte1 == b1
    shist[tid] = 0u;
    __syncthreads();
    for (int i = tid; i < cnt; i += 256)
        if ((int)(svals[i] >> 8) == b1) atomicAdd(&shist[svals[i] & 0xFFu], 1u);
    __syncthreads();
    v = shist[tid];
    e = scan_excl(v, tid, wsum);
    if (rank2 >= e && rank2 < e + v)
        stlow = ((unsigned)b1 << 8) | (unsigned)tid;  // low-16 threshold
    __syncthreads();

    // fix deferred rows: keep iff low16 strictly above threshold low16
    unsigned tlow = stlow;
    for (int i = tid; i < cnt; i += 256)
        g_keep[g_rows[b * CAP + i]] = (svals[i] > tlow) ? 1 : 0;
}

// -------- streaming prune: keep byte + fea stream only ---------------------
__global__ void k_prune(const float4* __restrict__ fea4,
                        float4* __restrict__ out4,
                        float* __restrict__ out_keep,
                        int total2, int writeKeep) {
    int gid = blockIdx.x * blockDim.x + threadIdx.x;

    // fold scratch re-zero for next invocation (graph replay determinism)
    {
        const int ZW = (MAXB * NBIN) / 4;  // uint4 words in g_hist1
        if (gid < ZW) {
            ((uint4*)g_hist1)[gid] = make_uint4(0u, 0u, 0u, 0u);
        } else if (gid < ZW + MAXB) {
            g_cnt[gid - ZW] = 0u;
        }
    }

    if (gid >= total2) return;
    int row = gid >> 3;  // 8 threads per 64-wide row (2 float4 each)
    bool keep = g_keep[row] != 0;

    float4 v0 = make_float4(0.f, 0.f, 0.f, 0.f);
    float4 v1 = v0;
    if (keep) {  // dropped rows: no fea read (output is zeros there)
        v0 = __ldcs(&fea4[2 * gid]);
        v1 = __ldcs(&fea4[2 * gid + 1]);
    }
    __stcs(&out4[2 * gid], v0);
    __stcs(&out4[2 * gid + 1], v1);
    if (writeKeep && ((gid & 7) == 0)) out_keep[row] = keep ? 1.0f : 0.0f;
}

extern "C" void kernel_launch(void* const* d_in, const int* in_sizes, int n_in,
                              void* d_out, int out_size) {
    const float* fea  = (const float*)d_in[0];
    const float* pred = (const float*)d_in[1];
    const int*   bid  = (const int*)d_in[2];
    const int*   tgt  = (const int*)d_in[3];
    const int n = in_sizes[1];      // N points
    const int C = in_sizes[0] / n;  // 64

    float* out_fea  = (float*)d_out;
    int writeKeep = (out_size >= n * C + n) ? 1 : 0;
    float* out_keep = out_fea + (size_t)n * C;

    int n4 = n / 4;
    k_hist1<<<(n4 + 255) / 256, 256>>>((const float4*)pred,
                                       (const uint4*)bid, n4);
    k_coarse<<<MAXB * NSEG, 256>>>();
    k_walk1<<<MAXB, 256>>>(tgt);
    k_collect<<<(n4 + 255) / 256, 256>>>((const float4*)pred,
                                         (const uint4*)bid, n4);
    k_final<<<MAXB, 256>>>();

    int total2 = n * (C / 8);  // ILP=2 work items
    k_prune<<<(total2 + 255) / 256, 256>>>((const float4*)fea,
                                           (float4*)d_out, out_keep,
                                           total2, writeKeep);
}